// round 7
// baseline (speedup 1.0000x reference)
#include <cuda_runtime.h>

// LDR toeplitz-displacement layer via FFT with 2-term real packing.
//   Hf = fft(D*H); Gf = fft(G); Xf = ifft(conj(D)*x)
//   t = D*fft(Hf.Xf) is REAL => pack two terms: z = u1 + i*u2,
//   W = fft(D.fft(z)) = Tf1 + i*Tf2 (Tf Hermitian), unpack via reversed read.
//   out = Re(ifft(sum Gf.Tf)) / (2N).
// 3 kernels:
//   K1 prep (256 blk, NT=512): radix-8 Stockham FFTs -> g_Hf, g_Gf, g_Xf.
//   K2 chain (1024 blk, NT=256, 2 CTAs/SM): one packed chain per block,
//      radix-16 Stockham (2 smem exchanges/FFT), in-place digit-swapped DFT16
//      (no reorder copy), partial Gf.Tf -> g_P.
//   K3 reduce (128 blk, NT=256): sum 8 partials + IFFT + write out.

#define NN    4096
#define CIN   4
#define COUT  4
#define RANK  4
#define BATCH 32

// prep (radix-8, NT=512)
#define NTP   512
#define PIDX(i) ((i) + ((i) >> 3))
#define NPAD   4608
#define WSIZE  512
#define PREP_SMEM ((2 * NPAD + WSIZE) * (int)sizeof(float2))

// main (radix-16, NT=256)
#define NTM   256
#define PIDX16(i) ((i) + ((i) >> 4))
#define NPAD16 4352
#define W16SIZE 256
#define MAIN_SMEM ((2 * NPAD16 + W16SIZE) * (int)sizeof(float2))

#define NCHAIN 1024   // (cout*batch) * (cin*rank/2)

__device__ float2 g_Hf[CIN*COUT*RANK][NN];   // 2 MB
__device__ float2 g_Gf[CIN*COUT*RANK][NN];   // 2 MB
__device__ float2 g_Xf[CIN*BATCH][NN];       // 4 MB
__device__ float2 g_P[NCHAIN][NN];           // 32 MB partials

__device__ __forceinline__ float2 cmul(float2 a, float2 b) {
    return make_float2(a.x*b.x - a.y*b.y, a.x*b.y + a.y*b.x);
}
__device__ __forceinline__ float2 cadd(float2 a, float2 b) { return make_float2(a.x+b.x, a.y+b.y); }
__device__ __forceinline__ float2 csub(float2 a, float2 b) { return make_float2(a.x-b.x, a.y-b.y); }

// ======================= prep: radix-8 Stockham (as R4) =====================

template<int INV>
__device__ __forceinline__ void bf8(float2 v[8]) {
    const float C = 0.70710678118654752440f;
    float2 e0,e1,e2,e3,o0,o1,o2,o3;
    {
        float2 t0 = cadd(v[0], v[4]);
        float2 t1 = csub(v[0], v[4]);
        float2 t2 = cadd(v[2], v[6]);
        float2 d  = csub(v[2], v[6]);
        float2 t3 = INV ? make_float2(-d.y, d.x) : make_float2(d.y, -d.x);
        e0 = cadd(t0,t2); e1 = cadd(t1,t3); e2 = csub(t0,t2); e3 = csub(t1,t3);
    }
    {
        float2 t0 = cadd(v[1], v[5]);
        float2 t1 = csub(v[1], v[5]);
        float2 t2 = cadd(v[3], v[7]);
        float2 d  = csub(v[3], v[7]);
        float2 t3 = INV ? make_float2(-d.y, d.x) : make_float2(d.y, -d.x);
        o0 = cadd(t0,t2); o1 = cadd(t1,t3); o2 = csub(t0,t2); o3 = csub(t1,t3);
    }
    float2 w1o, w2o, w3o;
    if (!INV) {
        w1o = make_float2(C*(o1.x + o1.y), C*(o1.y - o1.x));
        w2o = make_float2(o2.y, -o2.x);
        w3o = make_float2(C*(o3.y - o3.x), C*(-(o3.x + o3.y)));
    } else {
        w1o = make_float2(C*(o1.x - o1.y), C*(o1.y + o1.x));
        w2o = make_float2(-o2.y, o2.x);
        w3o = make_float2(C*(-(o3.x + o3.y)), C*(o3.x - o3.y));
    }
    v[0] = cadd(e0, o0);  v[4] = csub(e0, o0);
    v[1] = cadd(e1, w1o); v[5] = csub(e1, w1o);
    v[2] = cadd(e2, w2o); v[6] = csub(e2, w2o);
    v[3] = cadd(e3, w3o); v[7] = csub(e3, w3o);
}

template<int INV>
__device__ __forceinline__ void stage_store8(float2 v[8], float2* __restrict__ sb,
                                             const float2* __restrict__ W,
                                             int u, int sshift) {
    bf8<INV>(v);
    const int s  = 1 << sshift;
    const int k1 = u & ~(s - 1);
    const int base = u + 7 * k1;
    float2 w1 = W[k1];
    if (INV) w1.y = -w1.y;
    const float2 w2 = cmul(w1, w1);
    const float2 w3 = cmul(w2, w1);
    const float2 w4 = cmul(w2, w2);
    const float2 w5 = cmul(w3, w2);
    const float2 w6 = cmul(w3, w3);
    const float2 w7 = cmul(w4, w3);
    sb[PIDX(base)]         = v[0];
    sb[PIDX(base + s)]     = cmul(v[1], w1);
    sb[PIDX(base + 2*s)]   = cmul(v[2], w2);
    sb[PIDX(base + 3*s)]   = cmul(v[3], w3);
    sb[PIDX(base + 4*s)]   = cmul(v[4], w4);
    sb[PIDX(base + 5*s)]   = cmul(v[5], w5);
    sb[PIDX(base + 6*s)]   = cmul(v[6], w6);
    sb[PIDX(base + 7*s)]   = cmul(v[7], w7);
}

__device__ __forceinline__ void stage_load8(float2 v[8], const float2* __restrict__ sb, int tid) {
#pragma unroll
    for (int k = 0; k < 8; ++k) v[k] = sb[PIDX(tid + 512 * k)];
}

template<int INV, int PAR>
__device__ __forceinline__ void fft4096r8(float2 v[8], float2* b0, float2* b1,
                                          const float2* __restrict__ W, int tid) {
    float2* A = PAR ? b1 : b0;
    float2* B = PAR ? b0 : b1;
    stage_store8<INV>(v, A, W, tid, 0);
    __syncthreads();
    stage_load8(v, A, tid);
    stage_store8<INV>(v, B, W, tid, 3);
    __syncthreads();
    stage_load8(v, B, tid);
    stage_store8<INV>(v, A, W, tid, 6);
    __syncthreads();
    stage_load8(v, A, tid);
    bf8<INV>(v);
}

__global__ void __launch_bounds__(NTP, 1) ldr_prep_kernel(const float* __restrict__ x,
                                                          const float* __restrict__ G,
                                                          const float* __restrict__ H)
{
    extern __shared__ float2 smem2[];
    float2* b0 = smem2;
    float2* b1 = smem2 + NPAD;
    float2* W  = smem2 + 2 * NPAD;
    const int tid = threadIdx.x;
    if (tid < WSIZE) {
        float s, c; sincospif((float)tid * (1.0f / 2048.0f), &s, &c);
        W[tid] = make_float2(c, -s);
    }
    __syncthreads();

    const int bid = blockIdx.x;
    float2 v[8];
    if (bid < 64) {                       // Hf = fft(D * H)
        const float* h = H + bid * NN;
#pragma unroll
        for (int k = 0; k < 8; ++k) {
            const int n = tid + 512 * k;
            float s, c; sincospif((float)n * (1.0f / 4096.0f), &s, &c);
            const float val = h[n];
            v[k] = make_float2(val * c, val * s);
        }
        fft4096r8<0,0>(v, b0, b1, W, tid);
#pragma unroll
        for (int k = 0; k < 8; ++k) g_Hf[bid][tid + 512 * k] = v[k];
    } else if (bid < 128) {               // Gf = fft(G)
        const float* g = G + (bid - 64) * NN;
#pragma unroll
        for (int k = 0; k < 8; ++k) v[k] = make_float2(g[tid + 512 * k], 0.0f);
        fft4096r8<0,0>(v, b0, b1, W, tid);
#pragma unroll
        for (int k = 0; k < 8; ++k) g_Gf[bid - 64][tid + 512 * k] = v[k];
    } else {                              // Xf = ifft(conj(D) * x) (with 1/N)
        const float* xp = x + (bid - 128) * NN;
#pragma unroll
        for (int k = 0; k < 8; ++k) {
            const int n = tid + 512 * k;
            float s, c; sincospif((float)n * (1.0f / 4096.0f), &s, &c);
            const float val = xp[n];
            v[k] = make_float2(val * c, -val * s);
        }
        fft4096r8<1,0>(v, b0, b1, W, tid);
        const float inv = 1.0f / (float)NN;
#pragma unroll
        for (int k = 0; k < 8; ++k)
            g_Xf[bid - 128][tid + 512 * k] = make_float2(v[k].x * inv, v[k].y * inv);
    }
}

// =================== radix-16, in-place digit-swapped DFT16 =================
// swap(m) = ((m&3)<<2) | (m>>2). dft16A: natural in -> X[k] at slot swap(k).
// dft16B: swapped in (data[n] at slot swap(n)) -> X[k] at slot k.
// Both twiddle slot m by W16^{(m&3)*(m>>2)}.

__device__ __constant__ int SW16[16] = {0,4,8,12, 1,5,9,13, 2,6,10,14, 3,7,11,15};

template<int INV>
__device__ __forceinline__ void dft4ip(float2& a, float2& b, float2& c, float2& d) {
    float2 t0 = cadd(a,c), t1 = csub(a,c), t2 = cadd(b,d), bd = csub(b,d);
    float2 t3 = INV ? make_float2(-bd.y, bd.x) : make_float2(bd.y, -bd.x);
    a = cadd(t0,t2); b = cadd(t1,t3); c = csub(t0,t2); d = csub(t1,t3);
}

template<int INV>
__device__ __forceinline__ void tw16ip(float2 v[16]) {
    const float C1 = 0.92387953251128675613f;
    const float S1 = 0.38268343236508977172f;
    const float CC = 0.70710678118654752440f;
#define TW(m, c, s) v[m] = cmul(v[m], make_float2((c), INV ? (s) : -(s)))
    TW(5,  C1,  S1);
    TW(6,  CC,  CC);
    TW(7,  S1,  C1);
    TW(9,  CC,  CC);
    TW(10, 0.0f, 1.0f);
    TW(11, -CC, CC);
    TW(13, S1,  C1);
    TW(14, -CC, CC);
    TW(15, -C1, -S1);
#undef TW
}

template<int INV>
__device__ __forceinline__ void dft16A(float2 v[16]) {
#pragma unroll
    for (int n0 = 0; n0 < 4; ++n0) dft4ip<INV>(v[n0], v[n0+4], v[n0+8], v[n0+12]);
    tw16ip<INV>(v);
#pragma unroll
    for (int q = 0; q < 4; ++q) dft4ip<INV>(v[4*q], v[4*q+1], v[4*q+2], v[4*q+3]);
}

template<int INV>
__device__ __forceinline__ void dft16B(float2 v[16]) {
#pragma unroll
    for (int q = 0; q < 4; ++q) dft4ip<INV>(v[4*q], v[4*q+1], v[4*q+2], v[4*q+3]);
    tw16ip<INV>(v);
#pragma unroll
    for (int n0 = 0; n0 < 4; ++n0) dft4ip<INV>(v[n0], v[n0+4], v[n0+8], v[n0+12]);
}

// shared store with stage twiddles w^k (powers of W[k1]); IN_SWAPPED selects
// dft16B (input already in swapped slots) vs dft16A (natural input).
template<int INV, int IN_SWAPPED>
__device__ __forceinline__ void stage_store16(float2 v[16], float2* __restrict__ sb,
                                              const float2* __restrict__ W,
                                              int u, int sshift) {
    if (IN_SWAPPED) dft16B<INV>(v); else dft16A<INV>(v);
    // after A: X[k] at slot SW16[k]; after B: X[k] at slot k.
    const int s  = 1 << sshift;
    const int k1 = u & ~(s - 1);
    const int base = u + 15 * k1;
    float2 w1 = W[k1];
    if (INV) w1.y = -w1.y;
    float2 wp2 = cmul(w1, w1);
    float2 wp3 = cmul(wp2, w1);
    float2 wp4 = cmul(wp2, wp2);
    float2 wp5 = cmul(wp3, wp2);
    float2 wp6 = cmul(wp3, wp3);
    float2 wp7 = cmul(wp4, wp3);
    float2 wp8 = cmul(wp4, wp4);
    float2 wk[16];
    wk[0] = make_float2(1.0f, 0.0f);
    wk[1] = w1;  wk[2] = wp2;  wk[3] = wp3;  wk[4] = wp4;
    wk[5] = wp5; wk[6] = wp6;  wk[7] = wp7;  wk[8] = wp8;
    wk[9]  = cmul(wp8, w1);
    wk[10] = cmul(wp8, wp2);
    wk[11] = cmul(wp8, wp3);
    wk[12] = cmul(wp8, wp4);
    wk[13] = cmul(wp8, wp5);
    wk[14] = cmul(wp8, wp6);
    wk[15] = cmul(wp8, wp7);
#pragma unroll
    for (int k = 0; k < 16; ++k) {
        const float2 o = IN_SWAPPED ? v[k] : v[SW16[k]];
        sb[PIDX16(base + k * s)] = (k == 0) ? o : cmul(o, wk[k]);
    }
}

__device__ __forceinline__ void stage_load16(float2 v[16], const float2* __restrict__ sb, int tid) {
#pragma unroll
    for (int k = 0; k < 16; ++k) v[k] = sb[PIDX16(tid + 256 * k)];
}

// ============================ K2: one packed chain ==========================

__global__ void __launch_bounds__(NTM, 2) ldr_chain_kernel()
{
    extern __shared__ float2 smem2[];
    float2* b0 = smem2;
    float2* b1 = smem2 + NPAD16;
    float2* W  = smem2 + 2 * NPAD16;
    const int tid = threadIdx.x;
    {   // W[k1] = W4096^{k1}, k1 < 256
        float s, c; sincospif((float)tid * (1.0f / 2048.0f), &s, &c);
        W[tid] = make_float2(c, -s);
    }
    float2 d0;
    { float s, c; sincospif((float)tid * (1.0f / 4096.0f), &s, &c); d0 = make_float2(c, s); }

    // e^{i*pi*k/16}
    const float e16c[16] = { 1.0f, 0.98078528040323044913f, 0.92387953251128675613f,
        0.83146961230254523708f, 0.70710678118654752440f, 0.55557023301960222474f,
        0.38268343236508977172f, 0.19509032201612826785f, 0.0f, -0.19509032201612826785f,
        -0.38268343236508977172f, -0.55557023301960222474f, -0.70710678118654752440f,
        -0.83146961230254523708f, -0.92387953251128675613f, -0.98078528040323044913f };
    const float e16s[16] = { 0.0f, 0.19509032201612826785f, 0.38268343236508977172f,
        0.55557023301960222474f, 0.70710678118654752440f, 0.83146961230254523708f,
        0.92387953251128675613f, 0.98078528040323044913f, 1.0f, 0.98078528040323044913f,
        0.92387953251128675613f, 0.83146961230254523708f, 0.70710678118654752440f,
        0.55557023301960222474f, 0.38268343236508977172f, 0.19509032201612826785f };

    // decode: blockIdx = jb*8 + (i*2 + sp)
    const int jb = blockIdx.x >> 3;
    const int cc = blockIdx.x & 7;
    const int i  = cc >> 1;
    const int sp = cc & 1;
    const int j  = jb >> 5;
    const int b  = jb & 31;
    const int r1 = (i * COUT + j) * RANK + 2 * sp;
    const float2* __restrict__ hf1 = g_Hf[r1];
    const float2* __restrict__ hf2 = g_Hf[r1 + 1];
    const float2* __restrict__ gf1 = g_Gf[r1];
    const float2* __restrict__ gf2 = g_Gf[r1 + 1];
    const float2* __restrict__ xf  = g_Xf[i * BATCH + b];

    // pack z = u1 + i*u2 (natural layout)
    float2 v[16];
#pragma unroll
    for (int k = 0; k < 16; ++k) {
        const int n = tid + 256 * k;
        const float2 xv = xf[n];
        const float2 u1 = cmul(hf1[n], xv);
        const float2 u2 = cmul(hf2[n], xv);
        v[k] = make_float2(u1.x - u2.y, u1.y + u2.x);
    }
    __syncthreads();   // W table visible

    // fft #1
    stage_store16<0,0>(v, b0, W, tid, 0);
    __syncthreads();
    stage_load16(v, b0, tid);
    stage_store16<0,0>(v, b1, W, tid, 4);
    __syncthreads();
    stage_load16(v, b1, tid);
    dft16A<0>(v);                          // state: swapped
    // D multiply in swapped slots: slot m holds n = tid + 256*swap(m)
#pragma unroll
    for (int m = 0; m < 16; ++m)
        v[m] = cmul(v[m], cmul(d0, make_float2(e16c[SW16[m]], e16s[SW16[m]])));
    // fft #2 (input swapped -> use B variant in stage 1)
    stage_store16<0,1>(v, b0, W, tid, 0);
    __syncthreads();
    stage_load16(v, b0, tid);
    stage_store16<0,0>(v, b1, W, tid, 4);
    __syncthreads();
    stage_load16(v, b1, tid);
    dft16A<0>(v);                          // state: swapped

    // Hermitian unpack through b0 (last b0 readers are pre-barrier)
#pragma unroll
    for (int k = 0; k < 16; ++k) b0[PIDX16(tid + 256 * k)] = v[SW16[k]];
    __syncthreads();
    float2* __restrict__ P = g_P[blockIdx.x];
#pragma unroll
    for (int k = 0; k < 16; ++k) {
        const int n   = tid + 256 * k;
        const int rev = (NN - n) & (NN - 1);
        const float2 ws = b0[PIDX16(rev)];
        const float2 vk = v[SW16[k]];
        const float2 t1 = make_float2(vk.x + ws.x, vk.y - ws.y);   // 2*Tf1
        const float2 t2 = make_float2(vk.y + ws.y, ws.x - vk.x);   // 2*Tf2
        P[n] = cadd(cmul(gf1[n], t1), cmul(gf2[n], t2));
    }
}

// ====================== K3: reduce 8 partials + IFFT ========================

__global__ void __launch_bounds__(NTM, 2) ldr_reduce_kernel(float* __restrict__ out)
{
    extern __shared__ float2 smem2[];
    float2* b0 = smem2;
    float2* b1 = smem2 + NPAD16;
    float2* W  = smem2 + 2 * NPAD16;
    const int tid = threadIdx.x;
    {
        float s, c; sincospif((float)tid * (1.0f / 2048.0f), &s, &c);
        W[tid] = make_float2(c, -s);
    }

    const int jb = blockIdx.x;
    const int base = jb * 8;

    float2 v[16];
#pragma unroll
    for (int k = 0; k < 16; ++k) v[k] = g_P[base][tid + 256 * k];
#pragma unroll 1
    for (int t = 1; t < 8; ++t) {
        const float2* __restrict__ P = g_P[base + t];
#pragma unroll
        for (int k = 0; k < 16; ++k) v[k] = cadd(v[k], P[tid + 256 * k]);
    }
    __syncthreads();   // W table visible

    // ifft (no 1/N; folded with the packing 1/2 below)
    stage_store16<1,0>(v, b0, W, tid, 0);
    __syncthreads();
    stage_load16(v, b0, tid);
    stage_store16<1,0>(v, b1, W, tid, 4);
    __syncthreads();
    stage_load16(v, b1, tid);
    dft16A<1>(v);                          // state: swapped

    float* op = out + jb * NN;
    const float inv = 1.0f / (2.0f * (float)NN);
#pragma unroll
    for (int k = 0; k < 16; ++k) op[tid + 256 * k] = v[SW16[k]].x * inv;
}

extern "C" void kernel_launch(void* const* d_in, const int* in_sizes, int n_in,
                              void* d_out, int out_size)
{
    const float* x = (const float*)d_in[0];   // (4, 32, 4096)
    const float* G = (const float*)d_in[1];   // (4, 4, 4, 4096)
    const float* H = (const float*)d_in[2];   // (4, 4, 4, 4096)
    float* out = (float*)d_out;               // (4, 32, 4096)

    cudaFuncSetAttribute(ldr_prep_kernel,   cudaFuncAttributeMaxDynamicSharedMemorySize, PREP_SMEM);
    cudaFuncSetAttribute(ldr_chain_kernel,  cudaFuncAttributeMaxDynamicSharedMemorySize, MAIN_SMEM);
    cudaFuncSetAttribute(ldr_reduce_kernel, cudaFuncAttributeMaxDynamicSharedMemorySize, MAIN_SMEM);

    ldr_prep_kernel<<<256, NTP, PREP_SMEM>>>(x, G, H);
    ldr_chain_kernel<<<NCHAIN, NTM, MAIN_SMEM>>>();
    ldr_reduce_kernel<<<128, NTM, MAIN_SMEM>>>(out);
}